// round 13
// baseline (speedup 1.0000x reference)
#include <cuda_runtime.h>
#include <cuda_bf16.h>
#include <mma.h>

using namespace nvcuda;

#define N_TOTAL   1000000
#define DIM       128
#define S_SEG     125000
#define EPS       1e-13f
#define SEG_PER_BLOCK 128
#define SEG_PER_WARP  16
#define N_BLOCKS  ((S_SEG + SEG_PER_BLOCK - 1) / SEG_PER_BLOCK)   // 977

// ---------------------------------------------------------------------------
// Dynamic smem layout (bytes):
//   sZ    : float[128][128]      65536   per-block unnormalized weighted sums
//   sInv  : float[128]             512
//   sFrac : float[128]             512
//   Ahi   : bf16[128][40]        10240   (ld=40 elems)
//   Alo   : bf16[128][40]        10240
//   Bhi   : bf16[32][136]         8704   (ld=136 elems)
//   Blo   : bf16[32][136]         8704
// total = 104448 B  -> 2 blocks/SM (208 KB of 227 KB)
// ---------------------------------------------------------------------------
#define OFF_SZ    0
#define OFF_INV   65536
#define OFF_FRAC  66048
#define OFF_AHI   66560
#define OFF_ALO   76800
#define OFF_BHI   87040
#define OFF_BLO   95744
#define SMEM_BYTES 104448

__device__ __forceinline__ int lower_bound_idx(const int* __restrict__ idx, int n, int val) {
    int lo = 0, hi = n;
    while (lo < hi) {
        int mid = (lo + hi) >> 1;
        if (__ldg(&idx[mid]) < val) lo = mid + 1; else hi = mid;
    }
    return lo;
}

__device__ __forceinline__ void bf16_split(float v, __nv_bfloat16& hi, __nv_bfloat16& lo) {
    hi = __float2bfloat16(v);
    lo = __float2bfloat16(v - __bfloat162float(hi));
}

__device__ __forceinline__ void bf16_split2(float a, float b,
                                            __nv_bfloat162& hi2, __nv_bfloat162& lo2) {
    hi2 = __float22bfloat162_rn(make_float2(a, b));
    float2 hf = __bfloat1622float2(hi2);
    lo2 = __float22bfloat162_rn(make_float2(a - hf.x, b - hf.y));
}

__global__ void __launch_bounds__(256, 2)
fused_kernel(const float* __restrict__ x,
             const int*   __restrict__ index,
             const float* __restrict__ weights,
             const float* __restrict__ Wg,
             const float* __restrict__ bg,
             const float* __restrict__ Wm,
             const float* __restrict__ bm,
             float*       __restrict__ out)
{
    extern __shared__ char smem[];
    float* sZ    = reinterpret_cast<float*>(smem + OFF_SZ);
    float* sInv  = reinterpret_cast<float*>(smem + OFF_INV);
    float* sFrac = reinterpret_cast<float*>(smem + OFF_FRAC);
    __nv_bfloat16* Ahi = reinterpret_cast<__nv_bfloat16*>(smem + OFF_AHI);
    __nv_bfloat16* Alo = reinterpret_cast<__nv_bfloat16*>(smem + OFF_ALO);
    __nv_bfloat16* Bhi = reinterpret_cast<__nv_bfloat16*>(smem + OFF_BHI);
    __nv_bfloat16* Blo = reinterpret_cast<__nv_bfloat16*>(smem + OFF_BLO);

    const int t    = threadIdx.x;
    const int wid  = t >> 5;
    const int lane = t & 31;
    // clamp: last block overlaps previous; overlapping rows are recomputed
    // identically and written twice with identical values (deterministic).
    const int s0 = min(blockIdx.x * SEG_PER_BLOCK, S_SEG - SEG_PER_BLOCK);

    // ---- Phase 0: zero Z + denom (denom parked in sInv for now) ----
    {
        float4* z4 = reinterpret_cast<float4*>(sZ);
        #pragma unroll
        for (int i = 0; i < 16; ++i) z4[t + i * 256] = make_float4(0.f, 0.f, 0.f, 0.f);
        if (t < SEG_PER_BLOCK) sInv[t] = 0.f;
    }
    __syncthreads();

    // ---- Phase 1+2: per-warp gate + segment accumulation into smem ----
    // Warp w exclusively owns segments [s0+16w, s0+16w+16): plain stores, no atomics.
    {
        const int seg_lo = s0 + wid * SEG_PER_WARP;
        const int seg_hi = seg_lo + SEG_PER_WARP;
        const int w_start = lower_bound_idx(index, N_TOTAL, seg_lo);
        const int w_end   = lower_bound_idx(index, N_TOTAL, seg_hi);

        if (w_start < w_end) {
            const float4 wg  = reinterpret_cast<const float4*>(Wg)[lane];
            const float  bg0 = __ldg(bg);
            const float4* __restrict__ x4 = reinterpret_cast<const float4*>(x);

            int    cur  = __ldg(&index[w_start]);
            float4 acc  = make_float4(0.f, 0.f, 0.f, 0.f);
            float  esum = 0.f;

            auto flush = [&](int seg) {
                *reinterpret_cast<float4*>(&sZ[(seg - s0) * DIM + lane * 4]) = acc;
                if (lane == 0) sInv[seg - s0] = esum;   // denom parked here
            };
            auto step = [&](int seg, float e, const float4& xv) {
                if (seg != cur) {
                    flush(cur);
                    cur = seg;
                    acc = make_float4(0.f, 0.f, 0.f, 0.f);
                    esum = 0.f;
                }
                acc.x += e * xv.x;
                acc.y += e * xv.y;
                acc.z += e * xv.z;
                acc.w += e * xv.w;
                esum += e;
            };

            int n = w_start;
            for (; n + 3 < w_end; n += 4) {
                float4 xv0 = x4[(size_t)(n + 0) * 32 + lane];
                float4 xv1 = x4[(size_t)(n + 1) * 32 + lane];
                float4 xv2 = x4[(size_t)(n + 2) * 32 + lane];
                float4 xv3 = x4[(size_t)(n + 3) * 32 + lane];
                int sg0 = __ldg(&index[n + 0]);
                int sg1 = __ldg(&index[n + 1]);
                int sg2 = __ldg(&index[n + 2]);
                int sg3 = __ldg(&index[n + 3]);
                float w0 = __ldg(&weights[n + 0]);
                float w1 = __ldg(&weights[n + 1]);
                float w2 = __ldg(&weights[n + 2]);
                float w3 = __ldg(&weights[n + 3]);

                float d0 = xv0.x * wg.x + xv0.y * wg.y + xv0.z * wg.z + xv0.w * wg.w;
                float d1 = xv1.x * wg.x + xv1.y * wg.y + xv1.z * wg.z + xv1.w * wg.w;
                float d2 = xv2.x * wg.x + xv2.y * wg.y + xv2.z * wg.z + xv2.w * wg.w;
                float d3 = xv3.x * wg.x + xv3.y * wg.y + xv3.z * wg.z + xv3.w * wg.w;

                #pragma unroll
                for (int o = 16; o; o >>= 1) {
                    d0 += __shfl_xor_sync(0xFFFFFFFFu, d0, o);
                    d1 += __shfl_xor_sync(0xFFFFFFFFu, d1, o);
                    d2 += __shfl_xor_sync(0xFFFFFFFFu, d2, o);
                    d3 += __shfl_xor_sync(0xFFFFFFFFu, d3, o);
                }

                float e0 = w0 * __expf(d0 + bg0);
                float e1 = w1 * __expf(d1 + bg0);
                float e2 = w2 * __expf(d2 + bg0);
                float e3 = w3 * __expf(d3 + bg0);

                if ((sg0 == cur) && (sg3 == cur)) {   // sorted: all four equal
                    acc.x += e0 * xv0.x + e1 * xv1.x + e2 * xv2.x + e3 * xv3.x;
                    acc.y += e0 * xv0.y + e1 * xv1.y + e2 * xv2.y + e3 * xv3.y;
                    acc.z += e0 * xv0.z + e1 * xv1.z + e2 * xv2.z + e3 * xv3.z;
                    acc.w += e0 * xv0.w + e1 * xv1.w + e2 * xv2.w + e3 * xv3.w;
                    esum  += e0 + e1 + e2 + e3;
                } else {
                    step(sg0, e0, xv0);
                    step(sg1, e1, xv1);
                    step(sg2, e2, xv2);
                    step(sg3, e3, xv3);
                }
            }
            for (; n < w_end; ++n) {     // tail
                float4 xv = x4[(size_t)n * 32 + lane];
                int   sg = __ldg(&index[n]);
                float wn = __ldg(&weights[n]);
                float d  = xv.x * wg.x + xv.y * wg.y + xv.z * wg.z + xv.w * wg.w;
                #pragma unroll
                for (int o = 16; o; o >>= 1) d += __shfl_xor_sync(0xFFFFFFFFu, d, o);
                float e = wn * __expf(d + bg0);
                step(sg, e, xv);
            }
            flush(cur);
        }
    }
    __syncthreads();

    // ---- Phase 3a: denom -> inv / frac ----
    if (t < SEG_PER_BLOCK) {
        float d  = sInv[t];              // denom was parked in sInv
        float iv = 1.0f / (d + EPS);
        sInv[t]  = iv;
        sFrac[t] = d * iv;
    }
    __syncthreads();

    // ---- Phase 3b: tensor-core GEMM (2-term bf16 split), A from smem Z ----
    wmma::fragment<wmma::accumulator, 16, 16, 16, float> acc[8];
    #pragma unroll
    for (int nt = 0; nt < 8; ++nt) wmma::fill_fragment(acc[nt], 0.0f);

    wmma::fragment<wmma::matrix_a, 16, 16, 16, __nv_bfloat16, wmma::row_major> a_hi, a_lo;
    wmma::fragment<wmma::matrix_b, 16, 16, 16, __nv_bfloat16, wmma::row_major> b_hi, b_lo;

    for (int kc = 0; kc < DIM; kc += 32) {
        // convert A chunk [128 rows][32 k] from sZ (scaled by inv)
        #pragma unroll
        for (int i = 0; i < 4; ++i) {
            int f   = t + i * 256;
            int row = f >> 3;
            int c0  = (f & 7) * 4;
            float4 v = *reinterpret_cast<const float4*>(&sZ[row * DIM + kc + c0]);
            float iv = sInv[row];
            v.x *= iv; v.y *= iv; v.z *= iv; v.w *= iv;
            __nv_bfloat162 h01, l01, h23, l23;
            bf16_split2(v.x, v.y, h01, l01);
            bf16_split2(v.z, v.w, h23, l23);
            *reinterpret_cast<__nv_bfloat162*>(&Ahi[row * 40 + c0])     = h01;
            *reinterpret_cast<__nv_bfloat162*>(&Ahi[row * 40 + c0 + 2]) = h23;
            *reinterpret_cast<__nv_bfloat162*>(&Alo[row * 40 + c0])     = l01;
            *reinterpret_cast<__nv_bfloat162*>(&Alo[row * 40 + c0 + 2]) = l23;
        }
        // convert B chunk [32 k][128 cols] from Wm (L2-resident after wave 1)
        #pragma unroll
        for (int i = 0; i < 4; ++i) {
            int f   = t + i * 256;
            int row = f >> 5;
            int c0  = (f & 31) * 4;
            float4 v = *reinterpret_cast<const float4*>(&Wm[(size_t)(kc + row) * DIM + c0]);
            __nv_bfloat162 h01, l01, h23, l23;
            bf16_split2(v.x, v.y, h01, l01);
            bf16_split2(v.z, v.w, h23, l23);
            *reinterpret_cast<__nv_bfloat162*>(&Bhi[row * 136 + c0])     = h01;
            *reinterpret_cast<__nv_bfloat162*>(&Bhi[row * 136 + c0 + 2]) = h23;
            *reinterpret_cast<__nv_bfloat162*>(&Blo[row * 136 + c0])     = l01;
            *reinterpret_cast<__nv_bfloat162*>(&Blo[row * 136 + c0 + 2]) = l23;
        }
        __syncthreads();

        #pragma unroll
        for (int ks = 0; ks < 2; ++ks) {
            wmma::load_matrix_sync(a_hi, &Ahi[wid * 16 * 40 + ks * 16], 40);
            wmma::load_matrix_sync(a_lo, &Alo[wid * 16 * 40 + ks * 16], 40);
            #pragma unroll
            for (int nt = 0; nt < 8; ++nt) {
                wmma::load_matrix_sync(b_hi, &Bhi[ks * 16 * 136 + nt * 16], 136);
                wmma::load_matrix_sync(b_lo, &Blo[ks * 16 * 136 + nt * 16], 136);
                wmma::mma_sync(acc[nt], a_hi, b_hi, acc[nt]);
                wmma::mma_sync(acc[nt], a_lo, b_hi, acc[nt]);
                wmma::mma_sync(acc[nt], a_hi, b_lo, acc[nt]);
            }
        }
        __syncthreads();
    }

    // ---- bias step: out += frac[row] * bm[col], one K=16 MMA ----
    for (int idx = t; idx < 128 * 16; idx += 256) {
        int r = idx >> 4, c = idx & 15;
        float v = (c == 0) ? sFrac[r] : 0.0f;
        bf16_split(v, Ahi[r * 40 + c], Alo[r * 40 + c]);
    }
    for (int idx = t; idx < 16 * 128; idx += 256) {
        int r = idx >> 7, c = idx & 127;
        float v = (r == 0) ? __ldg(&bm[c]) : 0.0f;
        bf16_split(v, Bhi[r * 136 + c], Blo[r * 136 + c]);
    }
    __syncthreads();

    wmma::load_matrix_sync(a_hi, &Ahi[wid * 16 * 40], 40);
    wmma::load_matrix_sync(a_lo, &Alo[wid * 16 * 40], 40);
    #pragma unroll
    for (int nt = 0; nt < 8; ++nt) {
        wmma::load_matrix_sync(b_hi, &Bhi[nt * 16], 136);
        wmma::load_matrix_sync(b_lo, &Blo[nt * 16], 136);
        wmma::mma_sync(acc[nt], a_hi, b_hi, acc[nt]);
        wmma::mma_sync(acc[nt], a_lo, b_hi, acc[nt]);
        wmma::mma_sync(acc[nt], a_hi, b_lo, acc[nt]);
    }

    // ---- store (all rows valid thanks to the s0 clamp) ----
    #pragma unroll
    for (int nt = 0; nt < 8; ++nt) {
        wmma::store_matrix_sync(out + (size_t)(s0 + wid * 16) * DIM + nt * 16,
                                acc[nt], DIM, wmma::mem_row_major);
    }
}

// ---------------------------------------------------------------------------
// Launch: inputs (metadata order): x, index, weights, Wg, bg, Wm, bm
// ---------------------------------------------------------------------------
extern "C" void kernel_launch(void* const* d_in, const int* in_sizes, int n_in,
                              void* d_out, int out_size)
{
    const float* x       = (const float*)d_in[0];
    const int*   index   = (const int*)  d_in[1];
    const float* weights = (const float*)d_in[2];
    const float* Wg      = (const float*)d_in[3];
    const float* bg      = (const float*)d_in[4];
    const float* Wm      = (const float*)d_in[5];
    const float* bm      = (const float*)d_in[6];
    float*       out     = (float*)d_out;

    cudaFuncSetAttribute(fused_kernel,
                         cudaFuncAttributeMaxDynamicSharedMemorySize, SMEM_BYTES);

    fused_kernel<<<N_BLOCKS, 256, SMEM_BYTES>>>(x, index, weights, Wg, bg, Wm, bm, out);
}

// round 14
// speedup vs baseline: 1.1946x; 1.1946x over previous
#include <cuda_runtime.h>
#include <cuda_bf16.h>
#include <mma.h>

using namespace nvcuda;

#define N_TOTAL   1000000
#define DIM       128
#define S_SEG     125000
#define EPS       1e-13f
#define SEG_PER_BLOCK 64
#define SEG_PER_WARP  8
#define N_BLOCKS  ((S_SEG + SEG_PER_BLOCK - 1) / SEG_PER_BLOCK)   // 1954

// ---------------------------------------------------------------------------
// Dynamic smem layout (bytes):
//   sZ    : float[64][128]       32768
//   sInv  : float[64]              256
//   sFrac : float[64]              256
//   Ahi   : bf16[64][40]          5120   (ld=40 elems)
//   Alo   : bf16[64][40]          5120
//   Bhi   : bf16[32][136]         8704   (ld=136 elems)
//   Blo   : bf16[32][136]         8704
// total = 60928 B -> 3 CTAs/SM (183 KB of 227 KB), launch_bounds(256,3)
// ---------------------------------------------------------------------------
#define OFF_SZ    0
#define OFF_INV   32768
#define OFF_FRAC  33024
#define OFF_AHI   33280
#define OFF_ALO   38400
#define OFF_BHI   43520
#define OFF_BLO   52224
#define SMEM_BYTES 60928

__device__ __forceinline__ int lower_bound_idx(const int* __restrict__ idx, int n, int val) {
    int lo = 0, hi = n;
    while (lo < hi) {
        int mid = (lo + hi) >> 1;
        if (__ldg(&idx[mid]) < val) lo = mid + 1; else hi = mid;
    }
    return lo;
}

__device__ __forceinline__ void bf16_split(float v, __nv_bfloat16& hi, __nv_bfloat16& lo) {
    hi = __float2bfloat16(v);
    lo = __float2bfloat16(v - __bfloat162float(hi));
}

__device__ __forceinline__ void bf16_split2(float a, float b,
                                            __nv_bfloat162& hi2, __nv_bfloat162& lo2) {
    hi2 = __float22bfloat162_rn(make_float2(a, b));
    float2 hf = __bfloat1622float2(hi2);
    lo2 = __float22bfloat162_rn(make_float2(a - hf.x, b - hf.y));
}

__global__ void __launch_bounds__(256, 3)
fused_kernel(const float* __restrict__ x,
             const int*   __restrict__ index,
             const float* __restrict__ weights,
             const float* __restrict__ Wg,
             const float* __restrict__ bg,
             const float* __restrict__ Wm,
             const float* __restrict__ bm,
             float*       __restrict__ out)
{
    extern __shared__ char smem[];
    float* sZ    = reinterpret_cast<float*>(smem + OFF_SZ);
    float* sInv  = reinterpret_cast<float*>(smem + OFF_INV);
    float* sFrac = reinterpret_cast<float*>(smem + OFF_FRAC);
    __nv_bfloat16* Ahi = reinterpret_cast<__nv_bfloat16*>(smem + OFF_AHI);
    __nv_bfloat16* Alo = reinterpret_cast<__nv_bfloat16*>(smem + OFF_ALO);
    __nv_bfloat16* Bhi = reinterpret_cast<__nv_bfloat16*>(smem + OFF_BHI);
    __nv_bfloat16* Blo = reinterpret_cast<__nv_bfloat16*>(smem + OFF_BLO);

    const int t    = threadIdx.x;
    const int wid  = t >> 5;
    const int lane = t & 31;
    // clamp: last block overlaps previous; overlapping rows are recomputed
    // identically and written twice with identical values (deterministic).
    const int s0 = min(blockIdx.x * SEG_PER_BLOCK, S_SEG - SEG_PER_BLOCK);

    // ---- Phase 0: zero Z + denom (denom parked in sInv for now) ----
    {
        float4* z4 = reinterpret_cast<float4*>(sZ);
        #pragma unroll
        for (int i = 0; i < 8; ++i) z4[t + i * 256] = make_float4(0.f, 0.f, 0.f, 0.f);
        if (t < SEG_PER_BLOCK) sInv[t] = 0.f;
    }
    __syncthreads();

    // ---- Phase 1+2: per-warp gate + segment accumulation into smem ----
    // Warp w exclusively owns segments [s0+8w, s0+8w+8): plain stores, no atomics.
    {
        const int seg_lo = s0 + wid * SEG_PER_WARP;
        const int seg_hi = seg_lo + SEG_PER_WARP;
        const int w_start = lower_bound_idx(index, N_TOTAL, seg_lo);
        const int w_end   = lower_bound_idx(index, N_TOTAL, seg_hi);

        if (w_start < w_end) {
            const float4 wg  = reinterpret_cast<const float4*>(Wg)[lane];
            const float  bg0 = __ldg(bg);
            const float4* __restrict__ x4 = reinterpret_cast<const float4*>(x);

            int    cur  = __ldg(&index[w_start]);
            float4 acc  = make_float4(0.f, 0.f, 0.f, 0.f);
            float  esum = 0.f;

            auto flush = [&](int seg) {
                *reinterpret_cast<float4*>(&sZ[(seg - s0) * DIM + lane * 4]) = acc;
                if (lane == 0) sInv[seg - s0] = esum;   // denom parked here
            };
            auto step = [&](int seg, float e, const float4& xv) {
                if (seg != cur) {
                    flush(cur);
                    cur = seg;
                    acc = make_float4(0.f, 0.f, 0.f, 0.f);
                    esum = 0.f;
                }
                acc.x += e * xv.x;
                acc.y += e * xv.y;
                acc.z += e * xv.z;
                acc.w += e * xv.w;
                esum += e;
            };

            int n = w_start;
            for (; n + 3 < w_end; n += 4) {
                float4 xv0 = x4[(size_t)(n + 0) * 32 + lane];
                float4 xv1 = x4[(size_t)(n + 1) * 32 + lane];
                float4 xv2 = x4[(size_t)(n + 2) * 32 + lane];
                float4 xv3 = x4[(size_t)(n + 3) * 32 + lane];
                int sg0 = __ldg(&index[n + 0]);
                int sg1 = __ldg(&index[n + 1]);
                int sg2 = __ldg(&index[n + 2]);
                int sg3 = __ldg(&index[n + 3]);
                float w0 = __ldg(&weights[n + 0]);
                float w1 = __ldg(&weights[n + 1]);
                float w2 = __ldg(&weights[n + 2]);
                float w3 = __ldg(&weights[n + 3]);

                float d0 = xv0.x * wg.x + xv0.y * wg.y + xv0.z * wg.z + xv0.w * wg.w;
                float d1 = xv1.x * wg.x + xv1.y * wg.y + xv1.z * wg.z + xv1.w * wg.w;
                float d2 = xv2.x * wg.x + xv2.y * wg.y + xv2.z * wg.z + xv2.w * wg.w;
                float d3 = xv3.x * wg.x + xv3.y * wg.y + xv3.z * wg.z + xv3.w * wg.w;

                #pragma unroll
                for (int o = 16; o; o >>= 1) {
                    d0 += __shfl_xor_sync(0xFFFFFFFFu, d0, o);
                    d1 += __shfl_xor_sync(0xFFFFFFFFu, d1, o);
                    d2 += __shfl_xor_sync(0xFFFFFFFFu, d2, o);
                    d3 += __shfl_xor_sync(0xFFFFFFFFu, d3, o);
                }

                float e0 = w0 * __expf(d0 + bg0);
                float e1 = w1 * __expf(d1 + bg0);
                float e2 = w2 * __expf(d2 + bg0);
                float e3 = w3 * __expf(d3 + bg0);

                if ((sg0 == cur) && (sg3 == cur)) {   // sorted: all four equal
                    acc.x += e0 * xv0.x + e1 * xv1.x + e2 * xv2.x + e3 * xv3.x;
                    acc.y += e0 * xv0.y + e1 * xv1.y + e2 * xv2.y + e3 * xv3.y;
                    acc.z += e0 * xv0.z + e1 * xv1.z + e2 * xv2.z + e3 * xv3.z;
                    acc.w += e0 * xv0.w + e1 * xv1.w + e2 * xv2.w + e3 * xv3.w;
                    esum  += e0 + e1 + e2 + e3;
                } else {
                    step(sg0, e0, xv0);
                    step(sg1, e1, xv1);
                    step(sg2, e2, xv2);
                    step(sg3, e3, xv3);
                }
            }
            for (; n < w_end; ++n) {     // tail
                float4 xv = x4[(size_t)n * 32 + lane];
                int   sg = __ldg(&index[n]);
                float wn = __ldg(&weights[n]);
                float d  = xv.x * wg.x + xv.y * wg.y + xv.z * wg.z + xv.w * wg.w;
                #pragma unroll
                for (int o = 16; o; o >>= 1) d += __shfl_xor_sync(0xFFFFFFFFu, d, o);
                float e = wn * __expf(d + bg0);
                step(sg, e, xv);
            }
            flush(cur);
        }
    }
    __syncthreads();

    // ---- Phase 3a: denom -> inv / frac ----
    if (t < SEG_PER_BLOCK) {
        float d  = sInv[t];              // denom was parked in sInv
        float iv = 1.0f / (d + EPS);
        sInv[t]  = iv;
        sFrac[t] = d * iv;
    }
    __syncthreads();

    // ---- Phase 3b: tensor-core GEMM (2-term bf16 split), A from smem Z ----
    // Warp layout over the 64x128 output: row_tile = wid>>1 (16 rows),
    // col_half = wid&1 (64 cols = 4 N-tiles). 4 accumulators per warp.
    const int row_tile = wid >> 1;         // 0..3
    const int col_half = wid & 1;          // 0..1

    wmma::fragment<wmma::accumulator, 16, 16, 16, float> acc[4];
    #pragma unroll
    for (int nt = 0; nt < 4; ++nt) wmma::fill_fragment(acc[nt], 0.0f);

    wmma::fragment<wmma::matrix_a, 16, 16, 16, __nv_bfloat16, wmma::row_major> a_hi, a_lo;
    wmma::fragment<wmma::matrix_b, 16, 16, 16, __nv_bfloat16, wmma::row_major> b_hi, b_lo;

    for (int kc = 0; kc < DIM; kc += 32) {
        // convert A chunk [64 rows][32 k] from sZ (scaled by inv): 512 float4
        #pragma unroll
        for (int i = 0; i < 2; ++i) {
            int f   = t + i * 256;
            int row = f >> 3;
            int c0  = (f & 7) * 4;
            float4 v = *reinterpret_cast<const float4*>(&sZ[row * DIM + kc + c0]);
            float iv = sInv[row];
            v.x *= iv; v.y *= iv; v.z *= iv; v.w *= iv;
            __nv_bfloat162 h01, l01, h23, l23;
            bf16_split2(v.x, v.y, h01, l01);
            bf16_split2(v.z, v.w, h23, l23);
            *reinterpret_cast<__nv_bfloat162*>(&Ahi[row * 40 + c0])     = h01;
            *reinterpret_cast<__nv_bfloat162*>(&Ahi[row * 40 + c0 + 2]) = h23;
            *reinterpret_cast<__nv_bfloat162*>(&Alo[row * 40 + c0])     = l01;
            *reinterpret_cast<__nv_bfloat162*>(&Alo[row * 40 + c0 + 2]) = l23;
        }
        // convert B chunk [32 k][128 cols] from Wm (L2-resident): 1024 float4
        #pragma unroll
        for (int i = 0; i < 4; ++i) {
            int f   = t + i * 256;
            int row = f >> 5;
            int c0  = (f & 31) * 4;
            float4 v = *reinterpret_cast<const float4*>(&Wm[(size_t)(kc + row) * DIM + c0]);
            __nv_bfloat162 h01, l01, h23, l23;
            bf16_split2(v.x, v.y, h01, l01);
            bf16_split2(v.z, v.w, h23, l23);
            *reinterpret_cast<__nv_bfloat162*>(&Bhi[row * 136 + c0])     = h01;
            *reinterpret_cast<__nv_bfloat162*>(&Bhi[row * 136 + c0 + 2]) = h23;
            *reinterpret_cast<__nv_bfloat162*>(&Blo[row * 136 + c0])     = l01;
            *reinterpret_cast<__nv_bfloat162*>(&Blo[row * 136 + c0 + 2]) = l23;
        }
        __syncthreads();

        #pragma unroll
        for (int ks = 0; ks < 2; ++ks) {
            wmma::load_matrix_sync(a_hi, &Ahi[row_tile * 16 * 40 + ks * 16], 40);
            wmma::load_matrix_sync(a_lo, &Alo[row_tile * 16 * 40 + ks * 16], 40);
            #pragma unroll
            for (int nt = 0; nt < 4; ++nt) {
                int colb = col_half * 64 + nt * 16;
                wmma::load_matrix_sync(b_hi, &Bhi[ks * 16 * 136 + colb], 136);
                wmma::load_matrix_sync(b_lo, &Blo[ks * 16 * 136 + colb], 136);
                wmma::mma_sync(acc[nt], a_hi, b_hi, acc[nt]);
                wmma::mma_sync(acc[nt], a_lo, b_hi, acc[nt]);
                wmma::mma_sync(acc[nt], a_hi, b_lo, acc[nt]);
            }
        }
        __syncthreads();
    }

    // ---- bias step: out += frac[row] * bm[col], one K=16 MMA ----
    for (int idx = t; idx < 64 * 16; idx += 256) {
        int r = idx >> 4, c = idx & 15;
        float v = (c == 0) ? sFrac[r] : 0.0f;
        bf16_split(v, Ahi[r * 40 + c], Alo[r * 40 + c]);
    }
    for (int idx = t; idx < 16 * 128; idx += 256) {
        int r = idx >> 7, c = idx & 127;
        float v = (r == 0) ? __ldg(&bm[c]) : 0.0f;
        bf16_split(v, Bhi[r * 136 + c], Blo[r * 136 + c]);
    }
    __syncthreads();

    wmma::load_matrix_sync(a_hi, &Ahi[row_tile * 16 * 40], 40);
    wmma::load_matrix_sync(a_lo, &Alo[row_tile * 16 * 40], 40);
    #pragma unroll
    for (int nt = 0; nt < 4; ++nt) {
        int colb = col_half * 64 + nt * 16;
        wmma::load_matrix_sync(b_hi, &Bhi[colb], 136);
        wmma::load_matrix_sync(b_lo, &Blo[colb], 136);
        wmma::mma_sync(acc[nt], a_hi, b_hi, acc[nt]);
        wmma::mma_sync(acc[nt], a_lo, b_hi, acc[nt]);
        wmma::mma_sync(acc[nt], a_hi, b_lo, acc[nt]);
    }

    // ---- store (all rows valid thanks to the s0 clamp) ----
    #pragma unroll
    for (int nt = 0; nt < 4; ++nt) {
        wmma::store_matrix_sync(
            out + (size_t)(s0 + row_tile * 16) * DIM + col_half * 64 + nt * 16,
            acc[nt], DIM, wmma::mem_row_major);
    }
}

// ---------------------------------------------------------------------------
// Launch: inputs (metadata order): x, index, weights, Wg, bg, Wm, bm
// ---------------------------------------------------------------------------
extern "C" void kernel_launch(void* const* d_in, const int* in_sizes, int n_in,
                              void* d_out, int out_size)
{
    const float* x       = (const float*)d_in[0];
    const int*   index   = (const int*)  d_in[1];
    const float* weights = (const float*)d_in[2];
    const float* Wg      = (const float*)d_in[3];
    const float* bg      = (const float*)d_in[4];
    const float* Wm      = (const float*)d_in[5];
    const float* bm      = (const float*)d_in[6];
    float*       out     = (float*)d_out;

    cudaFuncSetAttribute(fused_kernel,
                         cudaFuncAttributeMaxDynamicSharedMemorySize, SMEM_BYTES);

    fused_kernel<<<N_BLOCKS, 256, SMEM_BYTES>>>(x, index, weights, Wg, bg, Wm, bm, out);
}